// round 16
// baseline (speedup 1.0000x reference)
#include <cuda_runtime.h>
#include <cuda_bf16.h>
#include <mma.h>
#include <math.h>
#include <stdint.h>

#define N_NODES 100000
#define N_EDGES 1600000
#define H0N     50048

struct alignas(8) Edge { int s; float w; };

// ---------------- device scratch ----------------
__device__ float g_hA [N_NODES * 32];
__device__ float g_hB [N_NODES * 64];
__device__ float g_m  [N_NODES * 64];
__device__ float g_agg[N_NODES * 64];
__device__ float g_fc2T[128 * 10];
__device__ unsigned char g_wimg[262144];
__device__ int   g_deg [N_NODES];
__device__ int   g_rowptr[N_NODES + 1];
__device__ int   g_cursor[N_NODES];
__device__ Edge  g_e2[N_EDGES];
__device__ int   g_bsum[128];
__device__ int   g_bsumex[128];
__device__ int   g_is64;

#define OFF_W1   0
#define OFF_WIH1 15360
#define OFF_WHH1 30720
#define OFF_W2   46080
#define OFF_WIH2 101376
#define OFF_WHH2 156672
#define OFF_FC1  211968

// ---------------- helpers ----------------
#define LOG2E 1.4426950408889634f
#define LN2   0.6931471805599453f
__device__ __forceinline__ float ex2a_(float x) {
    float y; asm("ex2.approx.ftz.f32 %0, %1;" : "=f"(y) : "f"(x)); return y;
}
__device__ __forceinline__ float lg2a_(float x) {
    float y; asm("lg2.approx.ftz.f32 %0, %1;" : "=f"(y) : "f"(x)); return y;
}
__device__ __forceinline__ float rcpa_(float x) {
    float y; asm("rcp.approx.ftz.f32 %0, %1;" : "=f"(y) : "f"(x)); return y;
}
__device__ __forceinline__ float fsig_(float x) { return rcpa_(1.f + ex2a_(-LOG2E * x)); }
__device__ __forceinline__ float ftanh_(float x) {
    return 1.f - 2.f * rcpa_(1.f + ex2a_(2.f * LOG2E * x));
}
__device__ __forceinline__ float eluf_(float x) {
    return x > 0.f ? x : ex2a_(LOG2E * x) - 1.f;
}

// ---------------- preprocessing ----------------
__global__ void k_sniff_zero(const void* __restrict__ p, int* __restrict__ deg) {
    int i = blockIdx.x * 1024 + threadIdx.x;
    if (i < N_NODES) deg[i] = 0;
    if (blockIdx.x == 0) {
        __shared__ int s_bad;
        if (threadIdx.x == 0) s_bad = 0;
        __syncthreads();
        long long v = ((const long long*)p)[threadIdx.x];
        if (v < 0 || v >= N_NODES) atomicAdd(&s_bad, 1);
        __syncthreads();
        if (threadIdx.x == 0) g_is64 = (s_bad < 512) ? 1 : 0;
    }
}

__global__ void k_count(const void* __restrict__ eraw, int* __restrict__ deg) {
    int e = blockIdx.x * blockDim.x + threadIdx.x;
    if (e >= N_EDGES) return;
    int d = g_is64 ? (int)((const long long*)eraw)[N_EDGES + e]
                   : ((const int*)eraw)[N_EDGES + e];
    if ((unsigned)d < N_NODES) atomicAdd(&deg[d], 1);
}

__global__ void k_scan1(const int* __restrict__ deg, int* __restrict__ rowptr,
                        int* __restrict__ bsum) {
    __shared__ int warp_sums[32];
    int tid = threadIdx.x, lane = tid & 31, wid = tid >> 5;
    int i = blockIdx.x * 1024 + tid;
    int v = (i < N_NODES) ? deg[i] : 0;
    int x = v;
#pragma unroll
    for (int d = 1; d < 32; d <<= 1) {
        int t = __shfl_up_sync(0xffffffffu, x, d);
        if (lane >= d) x += t;
    }
    if (lane == 31) warp_sums[wid] = x;
    __syncthreads();
    if (wid == 0) {
        int s = warp_sums[lane];
#pragma unroll
        for (int d = 1; d < 32; d <<= 1) {
            int t = __shfl_up_sync(0xffffffffu, s, d);
            if (lane >= d) s += t;
        }
        warp_sums[lane] = s;
    }
    __syncthreads();
    int pre = (wid > 0) ? warp_sums[wid - 1] : 0;
    if (i < N_NODES) rowptr[i] = pre + x - v;
    if (tid == 1023) bsum[blockIdx.x] = pre + x;
}

__global__ void k_scan2(const int* __restrict__ bsum, int* __restrict__ bsumex,
                        int* __restrict__ rowptr, int nb) {
    __shared__ int warp_sums[4];
    int tid = threadIdx.x, lane = tid & 31, wid = tid >> 5;
    int v = (tid < nb) ? bsum[tid] : 0;
    int x = v;
#pragma unroll
    for (int d = 1; d < 32; d <<= 1) {
        int t = __shfl_up_sync(0xffffffffu, x, d);
        if (lane >= d) x += t;
    }
    if (lane == 31) warp_sums[wid] = x;
    __syncthreads();
    int off = 0;
    for (int w = 0; w < wid; w++) off += warp_sums[w];
    if (tid < nb) bsumex[tid] = off + x - v;
    if (tid == 127) rowptr[N_NODES] = off + x;
}

__global__ void k_scan3(int* __restrict__ rowptr, const int* __restrict__ bsumex,
                        int* __restrict__ cursor) {
    int i = blockIdx.x * blockDim.x + threadIdx.x;
    if (i < N_NODES) {
        int v = rowptr[i] + bsumex[i >> 10];
        rowptr[i] = v;
        cursor[i] = v;
    }
}

__global__ void k_place(const void* __restrict__ eraw, const float* __restrict__ ea,
                        int* __restrict__ cursor, Edge* __restrict__ e2) {
    int e = blockIdx.x * blockDim.x + threadIdx.x;
    if (e >= N_EDGES) return;
    int s, d;
    if (g_is64) {
        s = (int)((const long long*)eraw)[e];
        d = (int)((const long long*)eraw)[N_EDGES + e];
    } else {
        s = ((const int*)eraw)[e];
        d = ((const int*)eraw)[N_EDGES + e];
    }
    if ((unsigned)s >= N_NODES || (unsigned)d >= N_NODES) return;
    int pos = atomicAdd(&cursor[d], 1);
    Edge ed; ed.s = s; ed.w = ea[e];
    e2[pos] = ed;
}

// ---------------- single fused weight-prep kernel ----------------
__device__ __forceinline__ void prep_elem(const float* src, __nv_bfloat16* d16,
                                          int R, int K, int KP, int trans, int idx) {
    int r = idx / KP, k = idx - r * KP;
    float v = 0.f;
    if (k < K) v = trans ? src[k * R + r] : src[r * K + k];
    __nv_bfloat16 h = __float2bfloat16(v);
    d16[r * KP + k]          = h;
    d16[R * KP + r * KP + k] = __float2bfloat16(v - __bfloat162float(h));
}

__global__ void k_prep_all(const float* __restrict__ W1, const float* __restrict__ Wih1,
                           const float* __restrict__ Whh1, const float* __restrict__ W2,
                           const float* __restrict__ Wih2, const float* __restrict__ Whh2,
                           const float* __restrict__ fc1w, const float* __restrict__ fc2w,
                           unsigned char* __restrict__ wimg, float* __restrict__ fc2T) {
    int idx = blockIdx.x * blockDim.x + threadIdx.x;
    if (idx < 3840) {
        int i = idx / 1280, j = idx - i * 1280;
        prep_elem(W1 + i * 1024, (__nv_bfloat16*)(wimg + OFF_W1 + i * 5120), 32, 32, 40, 1, j);
    } else if (idx < 7680) {
        prep_elem(Wih1, (__nv_bfloat16*)(wimg + OFF_WIH1), 96, 32, 40, 0, idx - 3840);
    } else if (idx < 11520) {
        prep_elem(Whh1, (__nv_bfloat16*)(wimg + OFF_WHH1), 96, 32, 40, 0, idx - 7680);
    } else if (idx < 25344) {
        int j = idx - 11520;
        int i = j / 4608; j -= i * 4608;
        prep_elem(W2 + i * 4096, (__nv_bfloat16*)(wimg + OFF_W2 + i * 18432), 64, 64, 72, 1, j);
    } else if (idx < 39168) {
        prep_elem(Wih2, (__nv_bfloat16*)(wimg + OFF_WIH2), 192, 64, 72, 0, idx - 25344);
    } else if (idx < 52992) {
        prep_elem(Whh2, (__nv_bfloat16*)(wimg + OFF_WHH2), 192, 64, 72, 0, idx - 39168);
    } else if (idx < 62208) {
        prep_elem(fc1w, (__nv_bfloat16*)(wimg + OFF_FC1), 128, 64, 72, 0, idx - 52992);
    } else if (idx < 63488) {
        int j = idx - 62208;
        int r = j / 128, k = j - r * 128;
        fc2T[k * 10 + r] = fc2w[j];
    }
}

__global__ void k_init_h(const float* __restrict__ x, float* __restrict__ h) {
    int i = blockIdx.x * blockDim.x + threadIdx.x;
    if (i < N_NODES * 32) {
        int n = i >> 5, c = i & 31;
        h[i] = (c < 16) ? x[n * 16 + c] : 0.f;
    }
}

__global__ void k_pad_elu(const float* __restrict__ src, float* __restrict__ dst) {
    int i = blockIdx.x * blockDim.x + threadIdx.x;
    if (i < N_NODES * 64) {
        int n = i >> 6, c = i & 63;
        dst[i] = (c < 32) ? eluf_(src[n * 32 + c]) : 0.f;
    }
}

// ---------------- HMMA bf16x3 GEMM (round-0 msg) ----------------
template <int K, int RC>
__global__ void __launch_bounds__(256)
tgemm(const float* __restrict__ X, const __nv_bfloat16* __restrict__ Bh,
      const __nv_bfloat16* __restrict__ Bl, float* __restrict__ Y, int N, int Rtot) {
    using namespace nvcuda;
    constexpr int KP = K + 8;
    extern __shared__ unsigned char smem[];
    __nv_bfloat16* sAh = (__nv_bfloat16*)smem;
    __nv_bfloat16* sAl = sAh + 128 * KP;
    __nv_bfloat16* sBh = sAl + 128 * KP;
    __nv_bfloat16* sBl = sBh + RC * KP;
    float* sEp = (float*)smem;

    int tid = threadIdx.x, wid = tid >> 5;
    int n0 = blockIdx.x * 128;
    int c0 = blockIdx.y * RC;

    {
        const uint4* bh = (const uint4*)(Bh + (size_t)c0 * KP);
        const uint4* bl = (const uint4*)(Bl + (size_t)c0 * KP);
        uint4* dh = (uint4*)sBh;
        uint4* dl = (uint4*)sBl;
        for (int i = tid; i < (RC * KP) / 8; i += 256) { dh[i] = bh[i]; dl[i] = bl[i]; }
    }
    for (int i = tid; i < 128 * K; i += 256) {
        int r = i / K, k = i - r * K;
        int nn = n0 + r;
        float v = (nn < N) ? X[(size_t)nn * K + k] : 0.f;
        __nv_bfloat16 h = __float2bfloat16(v);
        sAh[r * KP + k] = h;
        sAl[r * KP + k] = __float2bfloat16(v - __bfloat162float(h));
    }
    __syncthreads();

    wmma::fragment<wmma::accumulator, 16, 16, 16, float> acc[RC / 16];
#pragma unroll
    for (int nc = 0; nc < RC / 16; nc++) wmma::fill_fragment(acc[nc], 0.f);

    int row0 = wid * 16;
#pragma unroll
    for (int kc = 0; kc < K / 16; kc++) {
        wmma::fragment<wmma::matrix_a, 16, 16, 16, __nv_bfloat16, wmma::row_major> ah, al;
        wmma::load_matrix_sync(ah, sAh + row0 * KP + kc * 16, KP);
        wmma::load_matrix_sync(al, sAl + row0 * KP + kc * 16, KP);
#pragma unroll
        for (int nc = 0; nc < RC / 16; nc++) {
            wmma::fragment<wmma::matrix_b, 16, 16, 16, __nv_bfloat16, wmma::col_major> bh, bl;
            wmma::load_matrix_sync(bh, sBh + nc * 16 * KP + kc * 16, KP);
            wmma::load_matrix_sync(bl, sBl + nc * 16 * KP + kc * 16, KP);
            wmma::mma_sync(acc[nc], ah, bh, acc[nc]);
            wmma::mma_sync(acc[nc], ah, bl, acc[nc]);
            wmma::mma_sync(acc[nc], al, bh, acc[nc]);
        }
    }

    __syncthreads();
#pragma unroll
    for (int nc = 0; nc < RC / 16; nc++) {
        wmma::store_matrix_sync(sEp + row0 * 20, acc[nc], 20, wmma::mem_row_major);
        __syncthreads();
        for (int i = tid; i < 128 * 16; i += 256) {
            int r = i >> 4, c = i & 15;
            int nn = n0 + r;
            if (nn < N) Y[(size_t)nn * Rtot + c0 + nc * 16 + c] = sEp[r * 20 + c];
        }
        __syncthreads();
    }
}

// ---------------- CSR gather-max (float4, node-range offset) ----------------
template <int C>
__global__ void k_gather(const float* __restrict__ m, const int* __restrict__ rowptr,
                         const Edge* __restrict__ e2, float* __restrict__ agg, int nbase) {
    int cx = threadIdx.x;
    int n = nbase + blockIdx.x * blockDim.y + threadIdx.y;
    if (n >= N_NODES) return;
    int beg = rowptr[n], end = rowptr[n + 1];
    float4 a0 = make_float4(-INFINITY, -INFINITY, -INFINITY, -INFINITY);
    float4 a1 = a0, a2 = a0, a3 = a0;
    int e = beg;
    for (; e + 3 < end; e += 4) {
        Edge d0 = e2[e], d1 = e2[e + 1], d2 = e2[e + 2], d3 = e2[e + 3];
        float4 v0 = *(const float4*)&m[(size_t)d0.s * C + 4 * cx];
        float4 v1 = *(const float4*)&m[(size_t)d1.s * C + 4 * cx];
        float4 v2 = *(const float4*)&m[(size_t)d2.s * C + 4 * cx];
        float4 v3 = *(const float4*)&m[(size_t)d3.s * C + 4 * cx];
        a0.x = fmaxf(a0.x, v0.x * d0.w); a0.y = fmaxf(a0.y, v0.y * d0.w);
        a0.z = fmaxf(a0.z, v0.z * d0.w); a0.w = fmaxf(a0.w, v0.w * d0.w);
        a1.x = fmaxf(a1.x, v1.x * d1.w); a1.y = fmaxf(a1.y, v1.y * d1.w);
        a1.z = fmaxf(a1.z, v1.z * d1.w); a1.w = fmaxf(a1.w, v1.w * d1.w);
        a2.x = fmaxf(a2.x, v2.x * d2.w); a2.y = fmaxf(a2.y, v2.y * d2.w);
        a2.z = fmaxf(a2.z, v2.z * d2.w); a2.w = fmaxf(a2.w, v2.w * d2.w);
        a3.x = fmaxf(a3.x, v3.x * d3.w); a3.y = fmaxf(a3.y, v3.y * d3.w);
        a3.z = fmaxf(a3.z, v3.z * d3.w); a3.w = fmaxf(a3.w, v3.w * d3.w);
    }
    for (; e < end; e++) {
        Edge d0 = e2[e];
        float4 v0 = *(const float4*)&m[(size_t)d0.s * C + 4 * cx];
        a0.x = fmaxf(a0.x, v0.x * d0.w); a0.y = fmaxf(a0.y, v0.y * d0.w);
        a0.z = fmaxf(a0.z, v0.z * d0.w); a0.w = fmaxf(a0.w, v0.w * d0.w);
    }
    float4 r;
    r.x = fmaxf(fmaxf(a0.x, a1.x), fmaxf(a2.x, a3.x));
    r.y = fmaxf(fmaxf(a0.y, a1.y), fmaxf(a2.y, a3.y));
    r.z = fmaxf(fmaxf(a0.z, a1.z), fmaxf(a2.z, a3.z));
    r.w = fmaxf(fmaxf(a0.w, a1.w), fmaxf(a2.w, a3.w));
    if (!isfinite(r.x)) r.x = 0.f;
    if (!isfinite(r.y)) r.y = 0.f;
    if (!isfinite(r.z)) r.z = 0.f;
    if (!isfinite(r.w)) r.w = 0.f;
    *(float4*)&agg[(size_t)n * C + 4 * cx] = r;
}

// ---------------- fused GRU (8 warps, fragment-resident combine) ----------------
// Gates in accumulator fragments; bias tiles loaded as accumulator fragments;
// r/z persist in registers; h' computed per-element vs fp32 h tile (sHf).
template <int C>
__global__ void __launch_bounds__(256, 2)
k_gru_mega(const float* __restrict__ agg, float* __restrict__ h,
           const __nv_bfloat16* __restrict__ Wih_h, const __nv_bfloat16* __restrict__ Wih_l,
           const __nv_bfloat16* __restrict__ Whh_h, const __nv_bfloat16* __restrict__ Whh_l,
           const float* __restrict__ bih, const float* __restrict__ bhh,
           const __nv_bfloat16* __restrict__ Wn_h, const __nv_bfloat16* __restrict__ Wn_l,
           float* __restrict__ mout, int nbase, int N) {
    using namespace nvcuda;
    constexpr int KP = C + 8;
    constexpr int NC = C / 16;
    constexpr int NCW = NC / 2;          // nc per warp-group (C>=32)
    constexpr int ABYTES = 4 * 64 * KP * 2;
    constexpr int HFBYTES = 64 * KP * 4;
    constexpr int BBYTES = 4 * C * KP * 2;
    extern __shared__ unsigned char smem[];
    __nv_bfloat16* sAh = (__nv_bfloat16*)smem;
    __nv_bfloat16* sAl = sAh + 64 * KP;
    __nv_bfloat16* sHh = sAl + 64 * KP;
    __nv_bfloat16* sHl = sHh + 64 * KP;
    float* sHf = (float*)(smem + ABYTES);                 // fp32 h, later h'
    unsigned char* wreg = smem + ABYTES + HFBYTES;
    __nv_bfloat16* sBih_h = (__nv_bfloat16*)wreg;
    __nv_bfloat16* sBih_l = sBih_h + C * KP;
    __nv_bfloat16* sBhh_h = sBih_l + C * KP;
    __nv_bfloat16* sBhh_l = sBhh_h + C * KP;
    float* sBI = (float*)(wreg + BBYTES);                 // [16][C] bias ih (gate g)
    float* sBH = sBI + 16 * C;                            // [16][C] bias hh

    int tid = threadIdx.x, wid = tid >> 5;
    int n0 = nbase + blockIdx.x * 64;
    int row0 = (wid >> 1) * 16;
    int ncb = (wid & 1) * NCW;

    // stage agg (bf16 hi/lo) + h (bf16 hi/lo + fp32)
    for (int i = tid; i < 64 * C; i += 256) {
        int r = i / C, k = i - r * C;
        int nn = n0 + r;
        float va = (nn < N) ? agg[(size_t)nn * C + k] : 0.f;
        float vh = (nn < N) ? h[(size_t)nn * C + k] : 0.f;
        __nv_bfloat16 ah = __float2bfloat16(va);
        sAh[r * KP + k] = ah;
        sAl[r * KP + k] = __float2bfloat16(va - __bfloat162float(ah));
        __nv_bfloat16 hh = __float2bfloat16(vh);
        sHh[r * KP + k] = hh;
        sHl[r * KP + k] = __float2bfloat16(vh - __bfloat162float(hh));
        sHf[r * KP + k] = vh;
    }
    __syncthreads();

    wmma::fragment<wmma::accumulator, 16, 16, 16, float> rfr[NCW], zfr[NCW];

#pragma unroll
    for (int g = 0; g < 3; g++) {
        // stage gate-g weights + bias tiles
        {
            const uint4* bih_h = (const uint4*)(Wih_h + (size_t)g * C * KP);
            const uint4* bih_l = (const uint4*)(Wih_l + (size_t)g * C * KP);
            const uint4* bhh_h = (const uint4*)(Whh_h + (size_t)g * C * KP);
            const uint4* bhh_l = (const uint4*)(Whh_l + (size_t)g * C * KP);
            uint4* d0 = (uint4*)sBih_h; uint4* d1 = (uint4*)sBih_l;
            uint4* d2 = (uint4*)sBhh_h; uint4* d3 = (uint4*)sBhh_l;
            for (int i = tid; i < (C * KP) / 8; i += 256) {
                d0[i] = bih_h[i]; d1[i] = bih_l[i];
                d2[i] = bhh_h[i]; d3[i] = bhh_l[i];
            }
            for (int i = tid; i < 16 * C; i += 256) {
                int c = i % C;
                sBI[i] = bih[g * C + c];
                sBH[i] = bhh[g * C + c];
            }
        }
        __syncthreads();

        wmma::fragment<wmma::accumulator, 16, 16, 16, float> accI[NCW], accH[NCW];
#pragma unroll
        for (int j = 0; j < NCW; j++) {
            wmma::fill_fragment(accI[j], 0.f);
            wmma::fill_fragment(accH[j], 0.f);
        }
#pragma unroll
        for (int kc = 0; kc < C / 16; kc++) {
            wmma::fragment<wmma::matrix_a, 16, 16, 16, __nv_bfloat16, wmma::row_major> ah, al, hh, hl;
            wmma::load_matrix_sync(ah, sAh + row0 * KP + kc * 16, KP);
            wmma::load_matrix_sync(al, sAl + row0 * KP + kc * 16, KP);
            wmma::load_matrix_sync(hh, sHh + row0 * KP + kc * 16, KP);
            wmma::load_matrix_sync(hl, sHl + row0 * KP + kc * 16, KP);
#pragma unroll
            for (int j = 0; j < NCW; j++) {
                int nc = ncb + j;
                wmma::fragment<wmma::matrix_b, 16, 16, 16, __nv_bfloat16, wmma::col_major> bh, bl;
                wmma::load_matrix_sync(bh, sBih_h + nc * 16 * KP + kc * 16, KP);
                wmma::load_matrix_sync(bl, sBih_l + nc * 16 * KP + kc * 16, KP);
                wmma::mma_sync(accI[j], ah, bh, accI[j]);
                wmma::mma_sync(accI[j], ah, bl, accI[j]);
                wmma::mma_sync(accI[j], al, bh, accI[j]);
                wmma::load_matrix_sync(bh, sBhh_h + nc * 16 * KP + kc * 16, KP);
                wmma::load_matrix_sync(bl, sBhh_l + nc * 16 * KP + kc * 16, KP);
                wmma::mma_sync(accH[j], hh, bh, accH[j]);
                wmma::mma_sync(accH[j], hh, bl, accH[j]);
                wmma::mma_sync(accH[j], hl, bh, accH[j]);
            }
        }

        // fragment-resident combine
#pragma unroll
        for (int j = 0; j < NCW; j++) {
            int nc = ncb + j;
            wmma::fragment<wmma::accumulator, 16, 16, 16, float> biI, biH;
            wmma::load_matrix_sync(biI, sBI + nc * 16, C, wmma::mem_row_major);
            wmma::load_matrix_sync(biH, sBH + nc * 16, C, wmma::mem_row_major);
            if (g == 0) {
#pragma unroll
                for (int t = 0; t < accI[j].num_elements; t++)
                    rfr[j].x[t] = fsig_(accI[j].x[t] + biI.x[t] + accH[j].x[t] + biH.x[t]);
            } else if (g == 1) {
#pragma unroll
                for (int t = 0; t < accI[j].num_elements; t++)
                    zfr[j].x[t] = fsig_(accI[j].x[t] + biI.x[t] + accH[j].x[t] + biH.x[t]);
            } else {
                wmma::fragment<wmma::accumulator, 16, 16, 16, float> hvf;
                wmma::load_matrix_sync(hvf, sHf + row0 * KP + nc * 16, KP, wmma::mem_row_major);
#pragma unroll
                for (int t = 0; t < accI[j].num_elements; t++) {
                    float nv = ftanh_(accI[j].x[t] + biI.x[t] +
                                      rfr[j].x[t] * (accH[j].x[t] + biH.x[t]));
                    float zz = zfr[j].x[t];
                    accI[j].x[t] = (1.f - zz) * nv + zz * hvf.x[t];
                }
                wmma::store_matrix_sync(sHf + row0 * KP + nc * 16, accI[j], KP, wmma::mem_row_major);
            }
        }
        __syncthreads();   // weights consumed; (g==2) sHf fully written
    }

    // write h' to global; restage bf16 hi/lo for phase 2
    for (int i = tid; i < 64 * C; i += 256) {
        int r = i / C, c = i - r * C;
        int nn = n0 + r;
        float hnew = sHf[r * KP + c];
        if (nn < N) h[(size_t)nn * C + c] = hnew;
        __nv_bfloat16 hh2 = __float2bfloat16(hnew);
        sAh[r * KP + c] = hh2;
        sAl[r * KP + c] = __float2bfloat16(hnew - __bfloat162float(hh2));
    }

    // ---- phase 2: m_next = h' @ Wn^T ----
    if (mout != nullptr) {
        __syncthreads();
        {
            const uint4* wh = (const uint4*)Wn_h;
            const uint4* wl = (const uint4*)Wn_l;
            uint4* d0 = (uint4*)sBih_h;
            uint4* d1 = (uint4*)sBih_l;
            for (int i = tid; i < (C * KP) / 8; i += 256) { d0[i] = wh[i]; d1[i] = wl[i]; }
        }
        __syncthreads();

        wmma::fragment<wmma::accumulator, 16, 16, 16, float> accM[NCW];
#pragma unroll
        for (int j = 0; j < NCW; j++) wmma::fill_fragment(accM[j], 0.f);
#pragma unroll
        for (int kc = 0; kc < C / 16; kc++) {
            wmma::fragment<wmma::matrix_a, 16, 16, 16, __nv_bfloat16, wmma::row_major> ah, al;
            wmma::load_matrix_sync(ah, sAh + row0 * KP + kc * 16, KP);
            wmma::load_matrix_sync(al, sAl + row0 * KP + kc * 16, KP);
#pragma unroll
            for (int j = 0; j < NCW; j++) {
                int nc = ncb + j;
                wmma::fragment<wmma::matrix_b, 16, 16, 16, __nv_bfloat16, wmma::col_major> bh, bl;
                wmma::load_matrix_sync(bh, sBih_h + nc * 16 * KP + kc * 16, KP);
                wmma::load_matrix_sync(bl, sBih_l + nc * 16 * KP + kc * 16, KP);
                wmma::mma_sync(accM[j], ah, bh, accM[j]);
                wmma::mma_sync(accM[j], ah, bl, accM[j]);
                wmma::mma_sync(accM[j], al, bh, accM[j]);
            }
        }
        __syncthreads();   // sHf free (h' already consumed for restage)
#pragma unroll
        for (int j = 0; j < NCW; j++) {
            int nc = ncb + j;
            wmma::store_matrix_sync(sHf + row0 * KP + nc * 16, accM[j], KP, wmma::mem_row_major);
        }
        __syncthreads();
        for (int i = tid; i < 64 * C; i += 256) {
            int r = i / C, c = i - r * C;
            int nn = n0 + r;
            if (nn < N) mout[(size_t)nn * C + c] = sHf[r * KP + c];
        }
    }
}

// ---------------- fused head: fc1 (elu in/out) + fc2 + log_softmax ----------------
__global__ void __launch_bounds__(256)
k_head(const float* __restrict__ X, const __nv_bfloat16* __restrict__ Bh,
       const __nv_bfloat16* __restrict__ Bl, const float* __restrict__ fc1b,
       const float* __restrict__ fc2t, const float* __restrict__ fc2b,
       float* __restrict__ out, int N) {
    using namespace nvcuda;
    constexpr int KP = 72;
    constexpr int HLD = 136;
    extern __shared__ unsigned char smem[];
    __nv_bfloat16* sAh = (__nv_bfloat16*)smem;
    __nv_bfloat16* sAl = sAh + 128 * KP;
    __nv_bfloat16* sBh = sAl + 128 * KP;
    __nv_bfloat16* sBl = sBh + 128 * KP;
    float* sHid = (float*)smem;
    float* sW2  = (float*)(smem + 73728);
    float* sB1  = sW2 + 1280;
    float* sB2  = sB1 + 128;

    int tid = threadIdx.x, wid = tid >> 5, lane = tid & 31;
    int n0 = blockIdx.x * 128;

    {
        const uint4* bh = (const uint4*)Bh;
        const uint4* bl = (const uint4*)Bl;
        uint4* dh = (uint4*)sBh;
        uint4* dl = (uint4*)sBl;
        for (int i = tid; i < (128 * KP) / 8; i += 256) { dh[i] = bh[i]; dl[i] = bl[i]; }
    }
    for (int i = tid; i < 1280; i += 256) sW2[i] = fc2t[i];
    if (tid < 128) sB1[tid] = fc1b[tid];
    if (tid < 10)  sB2[tid] = fc2b[tid];
    for (int i = tid; i < 128 * 64; i += 256) {
        int r = i >> 6, k = i & 63;
        int nn = n0 + r;
        float v = (nn < N) ? eluf_(X[(size_t)nn * 64 + k]) : 0.f;
        __nv_bfloat16 h = __float2bfloat16(v);
        sAh[r * KP + k] = h;
        sAl[r * KP + k] = __float2bfloat16(v - __bfloat162float(h));
    }
    __syncthreads();

    wmma::fragment<wmma::accumulator, 16, 16, 16, float> acc[8];
#pragma unroll
    for (int nc = 0; nc < 8; nc++) wmma::fill_fragment(acc[nc], 0.f);

    int row0 = wid * 16;
#pragma unroll
    for (int kc = 0; kc < 4; kc++) {
        wmma::fragment<wmma::matrix_a, 16, 16, 16, __nv_bfloat16, wmma::row_major> ah, al;
        wmma::load_matrix_sync(ah, sAh + row0 * KP + kc * 16, KP);
        wmma::load_matrix_sync(al, sAl + row0 * KP + kc * 16, KP);
#pragma unroll
        for (int nc = 0; nc < 8; nc++) {
            wmma::fragment<wmma::matrix_b, 16, 16, 16, __nv_bfloat16, wmma::col_major> bh, bl;
            wmma::load_matrix_sync(bh, sBh + nc * 16 * KP + kc * 16, KP);
            wmma::load_matrix_sync(bl, sBl + nc * 16 * KP + kc * 16, KP);
            wmma::mma_sync(acc[nc], ah, bh, acc[nc]);
            wmma::mma_sync(acc[nc], ah, bl, acc[nc]);
            wmma::mma_sync(acc[nc], al, bh, acc[nc]);
        }
    }
    __syncthreads();

#pragma unroll
    for (int nc = 0; nc < 8; nc++)
        wmma::store_matrix_sync(sHid + row0 * HLD + nc * 16, acc[nc], HLD, wmma::mem_row_major);
    __syncthreads();

    for (int nn = wid * 16; nn < wid * 16 + 16; nn++) {
        int node = n0 + nn;
        if (node >= N) continue;
        float a[10];
#pragma unroll
        for (int j = 0; j < 10; j++) a[j] = 0.f;
#pragma unroll
        for (int kk = 0; kk < 4; kk++) {
            int k = lane + kk * 32;
            float xv = eluf_(sHid[nn * HLD + k] + sB1[k]);
            const float* w = sW2 + k * 10;
#pragma unroll
            for (int j = 0; j < 10; j++) a[j] = fmaf(xv, w[j], a[j]);
        }
#pragma unroll
        for (int j = 0; j < 10; j++)
            for (int off = 16; off; off >>= 1) a[j] += __shfl_xor_sync(0xffffffffu, a[j], off);
        float mx = -INFINITY;
#pragma unroll
        for (int j = 0; j < 10; j++) { a[j] += sB2[j]; mx = fmaxf(mx, a[j]); }
        float se = 0.f;
#pragma unroll
        for (int j = 0; j < 10; j++) se += ex2a_(LOG2E * (a[j] - mx));
        float lse = mx + LN2 * lg2a_(se);
        if (lane < 10) out[(size_t)node * 10 + lane] = a[lane] - lse;
    }
}

// ---------------- launch ----------------
static inline int gdiv(int n) { return (n + 255) / 256; }

extern "C" void kernel_launch(void* const* d_in, const int* in_sizes, int n_in,
                              void* d_out, int out_size) {
    const float* x    = (const float*)d_in[0];
    const void*  eraw = d_in[1];
    const float* ea   = (const float*)d_in[2];
    const float* W1   = (const float*)d_in[3];
    const float* Wih1 = (const float*)d_in[4];
    const float* Whh1 = (const float*)d_in[5];
    const float* bih1 = (const float*)d_in[6];
    const float* bhh1 = (const float*)d_in[7];
    const float* W2   = (const float*)d_in[8];
    const float* Wih2 = (const float*)d_in[9];
    const float* Whh2 = (const float*)d_in[10];
    const float* bih2 = (const float*)d_in[11];
    const float* bhh2 = (const float*)d_in[12];
    const float* fc1w = (const float*)d_in[13];
    const float* fc1b = (const float*)d_in[14];
    const float* fc2w = (const float*)d_in[15];
    const float* fc2b = (const float*)d_in[16];
    float* out = (float*)d_out;

    float *hA, *hB, *m, *agg, *fc2T;
    unsigned char* wimg;
    Edge* e2;
    int *deg, *rowptr, *cursor, *bsum, *bsumex;
    cudaGetSymbolAddress((void**)&hA,    g_hA);
    cudaGetSymbolAddress((void**)&hB,    g_hB);
    cudaGetSymbolAddress((void**)&m,     g_m);
    cudaGetSymbolAddress((void**)&agg,   g_agg);
    cudaGetSymbolAddress((void**)&fc2T,  g_fc2T);
    cudaGetSymbolAddress((void**)&wimg,  g_wimg);
    cudaGetSymbolAddress((void**)&deg,   g_deg);
    cudaGetSymbolAddress((void**)&rowptr,g_rowptr);
    cudaGetSymbolAddress((void**)&cursor,g_cursor);
    cudaGetSymbolAddress((void**)&e2,    g_e2);
    cudaGetSymbolAddress((void**)&bsum,  g_bsum);
    cudaGetSymbolAddress((void**)&bsumex,g_bsumex);

    static cudaStream_t s1 = nullptr;
    static cudaEvent_t  ev[16];
    if (s1 == nullptr) {
        cudaStreamCreateWithFlags(&s1, cudaStreamNonBlocking);
        for (int i = 0; i < 16; i++)
            cudaEventCreateWithFlags(&ev[i], cudaEventDisableTiming);
    }
    const int E_FORK = 0, E_CSR = 1, E_M1 = 2, E_M2 = 3;
    int enext = 4;

    const int TB = 256;
    const int GM  = (N_NODES + 127) / 128;  // 782
    const int NB = (N_NODES + 1023) / 1024; // 98
    const int H1N = N_NODES - H0N;
    const int MB0 = H0N / 64;
    const int MB1 = (H1N + 63) / 64;

    const __nv_bfloat16* W1h[3];  const __nv_bfloat16* W1l[3];
    const __nv_bfloat16* W2h[3];  const __nv_bfloat16* W2l[3];
    for (int i = 0; i < 3; i++) {
        W1h[i] = (const __nv_bfloat16*)(wimg + OFF_W1 + i * 5120);
        W1l[i] = W1h[i] + 32 * 40;
        W2h[i] = (const __nv_bfloat16*)(wimg + OFF_W2 + i * 18432);
        W2l[i] = W2h[i] + 64 * 72;
    }
    const __nv_bfloat16* Wih1h = (const __nv_bfloat16*)(wimg + OFF_WIH1);
    const __nv_bfloat16* Wih1l = Wih1h + 96 * 40;
    const __nv_bfloat16* Whh1h = (const __nv_bfloat16*)(wimg + OFF_WHH1);
    const __nv_bfloat16* Whh1l = Whh1h + 96 * 40;
    const __nv_bfloat16* Wih2h = (const __nv_bfloat16*)(wimg + OFF_WIH2);
    const __nv_bfloat16* Wih2l = Wih2h + 192 * 72;
    const __nv_bfloat16* Whh2h = (const __nv_bfloat16*)(wimg + OFF_WHH2);
    const __nv_bfloat16* Whh2l = Whh2h + 192 * 72;
    const __nv_bfloat16* Fc1h  = (const __nv_bfloat16*)(wimg + OFF_FC1);
    const __nv_bfloat16* Fc1l  = Fc1h + 128 * 72;

    const int SM_32_32 = (128 + 32) * 40 * 4;
    const int SM_64_64 = (128 + 64) * 72 * 4;
    // mega smem: A(4*64*KP*2) + sHf(64*KP*4) + W(4*C*KP*2) + bias(2*16*C*4)
    const int MEGA32 = 4 * 64 * 40 * 2 + 64 * 40 * 4 + 4 * 32 * 40 * 2 + 2 * 16 * 32 * 4; // 45056
    const int MEGA64 = 4 * 64 * 72 * 2 + 64 * 72 * 4 + 4 * 64 * 72 * 2 + 2 * 16 * 64 * 4; // 100352
    const int SM_HEAD = 73728 + (1280 + 128 + 16) * 4;
    cudaFuncSetAttribute(tgemm<64, 64>, cudaFuncAttributeMaxDynamicSharedMemorySize, SM_64_64);
    cudaFuncSetAttribute(k_gru_mega<32>, cudaFuncAttributeMaxDynamicSharedMemorySize, MEGA32);
    cudaFuncSetAttribute(k_gru_mega<64>, cudaFuncAttributeMaxDynamicSharedMemorySize, MEGA64);
    cudaFuncSetAttribute(k_head, cudaFuncAttributeMaxDynamicSharedMemorySize, SM_HEAD);

    // ---- fork: CSR build on s1, overlapped with prep/init/tgemm0 ----
    cudaEventRecord(ev[E_FORK], 0);
    cudaStreamWaitEvent(s1, ev[E_FORK], 0);
    k_sniff_zero<<<NB, 1024, 0, s1>>>(eraw, deg);
    k_count<<<gdiv(N_EDGES), TB, 0, s1>>>(eraw, deg);
    k_scan1<<<NB, 1024, 0, s1>>>(deg, rowptr, bsum);
    k_scan2<<<1, 128, 0, s1>>>(bsum, bsumex, rowptr, NB);
    k_scan3<<<gdiv(N_NODES), TB, 0, s1>>>(rowptr, bsumex, cursor);
    k_place<<<gdiv(N_EDGES), TB, 0, s1>>>(eraw, ea, cursor, e2);
    cudaEventRecord(ev[E_CSR], s1);

    // main chain
    k_prep_all<<<gdiv(63488), TB>>>(W1, Wih1, Whh1, W2, Wih2, Whh2, fc1w, fc2w, wimg, fc2T);
    k_init_h<<<gdiv(N_NODES * 32), TB>>>(x, hA);
    tgemm<32, 32><<<dim3(GM, 1), 256, SM_32_32>>>(hA, W1h[0], W1l[0], m, N_NODES, 32);
    cudaEventRecord(ev[E_M1], 0);

    cudaStreamWaitEvent(0, ev[E_CSR], 0);
    cudaStreamWaitEvent(s1, ev[E_M1], 0);

    // ---- layer 1 (C=32), halves on two streams ----
    for (int i = 0; i < 3; i++) {
        const __nv_bfloat16* wnh = (i < 2) ? W1h[i + 1] : nullptr;
        const __nv_bfloat16* wnl = (i < 2) ? W1l[i + 1] : nullptr;
        float* mo = (i < 2) ? m : nullptr;
        { dim3 blk(8, 32);
          k_gather<32><<<H0N / 32, blk, 0, 0>>>(m, rowptr, e2, agg, 0);
          k_gather<32><<<(H1N + 31) / 32, blk, 0, s1>>>(m, rowptr, e2, agg, H0N); }
        k_gru_mega<32><<<MB0, 256, MEGA32, 0>>>(agg, hA, Wih1h, Wih1l, Whh1h, Whh1l,
                                                bih1, bhh1, wnh, wnl, mo, 0, N_NODES);
        k_gru_mega<32><<<MB1, 256, MEGA32, s1>>>(agg, hA, Wih1h, Wih1l, Whh1h, Whh1l,
                                                 bih1, bhh1, wnh, wnl, mo, H0N, N_NODES);
        cudaEventRecord(ev[enext], 0);
        cudaEventRecord(ev[enext + 1], s1);
        cudaStreamWaitEvent(0, ev[enext + 1], 0);
        cudaStreamWaitEvent(s1, ev[enext], 0);
        enext += 2;
    }

    k_pad_elu<<<gdiv(N_NODES * 64), TB>>>(hA, hB);
    tgemm<64, 64><<<dim3(GM, 1), 256, SM_64_64>>>(hB, W2h[0], W2l[0], m, N_NODES, 64);
    cudaEventRecord(ev[E_M2], 0);
    cudaStreamWaitEvent(s1, ev[E_M2], 0);

    // ---- layer 2 (C=64), halves on two streams ----
    for (int i = 0; i < 3; i++) {
        const __nv_bfloat16* wnh = (i < 2) ? W2h[i + 1] : nullptr;
        const __nv_bfloat16* wnl = (i < 2) ? W2l[i + 1] : nullptr;
        float* mo = (i < 2) ? m : nullptr;
        { dim3 blk(16, 16);
          k_gather<64><<<H0N / 16, blk, 0, 0>>>(m, rowptr, e2, agg, 0);
          k_gather<64><<<(H1N + 15) / 16, blk, 0, s1>>>(m, rowptr, e2, agg, H0N); }
        k_gru_mega<64><<<MB0, 256, MEGA64, 0>>>(agg, hB, Wih2h, Wih2l, Whh2h, Whh2l,
                                                bih2, bhh2, wnh, wnl, mo, 0, N_NODES);
        k_gru_mega<64><<<MB1, 256, MEGA64, s1>>>(agg, hB, Wih2h, Wih2l, Whh2h, Whh2l,
                                                 bih2, bhh2, wnh, wnl, mo, H0N, N_NODES);
        cudaEventRecord(ev[enext], 0);
        cudaEventRecord(ev[enext + 1], s1);
        cudaStreamWaitEvent(0, ev[enext + 1], 0);
        cudaStreamWaitEvent(s1, ev[enext], 0);
        enext += 2;
    }

    // ---- fused head ----
    k_head<<<GM, 256, SM_HEAD>>>(hB, Fc1h, Fc1l, fc1b, fc2T, fc2b, out, N_NODES);
}

// round 17
// speedup vs baseline: 1.0415x; 1.0415x over previous
#include <cuda_runtime.h>
#include <cuda_bf16.h>
#include <mma.h>
#include <math.h>
#include <stdint.h>

#define N_NODES 100000
#define N_EDGES 1600000
#define H0N     50048

struct alignas(8) Edge { int s; float w; };

// ---------------- device scratch ----------------
__device__ float g_hA [N_NODES * 32];
__device__ float g_hB [N_NODES * 64];
__device__ float g_m  [N_NODES * 64];
__device__ float g_agg[N_NODES * 64];
__device__ float g_fc2T[128 * 10];
__device__ unsigned char g_wimg[262144];
__device__ int   g_deg [N_NODES];
__device__ int   g_rowptr[N_NODES + 1];
__device__ int   g_cursor[N_NODES];
__device__ Edge  g_e2[N_EDGES];
__device__ int   g_bsum[128];
__device__ int   g_bsumex[128];
__device__ int   g_is64;

#define OFF_W1   0
#define OFF_WIH1 15360
#define OFF_WHH1 30720
#define OFF_W2   46080
#define OFF_WIH2 101376
#define OFF_WHH2 156672
#define OFF_FC1  211968

// ---------------- helpers ----------------
#define LOG2E 1.4426950408889634f
#define LN2   0.6931471805599453f
__device__ __forceinline__ float ex2a_(float x) {
    float y; asm("ex2.approx.ftz.f32 %0, %1;" : "=f"(y) : "f"(x)); return y;
}
__device__ __forceinline__ float lg2a_(float x) {
    float y; asm("lg2.approx.ftz.f32 %0, %1;" : "=f"(y) : "f"(x)); return y;
}
__device__ __forceinline__ float rcpa_(float x) {
    float y; asm("rcp.approx.ftz.f32 %0, %1;" : "=f"(y) : "f"(x)); return y;
}
__device__ __forceinline__ float fsig_(float x) { return rcpa_(1.f + ex2a_(-LOG2E * x)); }
__device__ __forceinline__ float ftanh_(float x) {
    return 1.f - 2.f * rcpa_(1.f + ex2a_(2.f * LOG2E * x));
}
__device__ __forceinline__ float eluf_(float x) {
    return x > 0.f ? x : ex2a_(LOG2E * x) - 1.f;
}

// ---------------- preprocessing ----------------
__global__ void k_sniff_zero(const void* __restrict__ p, int* __restrict__ deg) {
    int i = blockIdx.x * 1024 + threadIdx.x;
    if (i < N_NODES) deg[i] = 0;
    if (blockIdx.x == 0) {
        __shared__ int s_bad;
        if (threadIdx.x == 0) s_bad = 0;
        __syncthreads();
        long long v = ((const long long*)p)[threadIdx.x];
        if (v < 0 || v >= N_NODES) atomicAdd(&s_bad, 1);
        __syncthreads();
        if (threadIdx.x == 0) g_is64 = (s_bad < 512) ? 1 : 0;
    }
}

__global__ void k_count(const void* __restrict__ eraw, int* __restrict__ deg) {
    int e = blockIdx.x * blockDim.x + threadIdx.x;
    if (e >= N_EDGES) return;
    int d = g_is64 ? (int)((const long long*)eraw)[N_EDGES + e]
                   : ((const int*)eraw)[N_EDGES + e];
    if ((unsigned)d < N_NODES) atomicAdd(&deg[d], 1);
}

__global__ void k_scan1(const int* __restrict__ deg, int* __restrict__ rowptr,
                        int* __restrict__ bsum) {
    __shared__ int warp_sums[32];
    int tid = threadIdx.x, lane = tid & 31, wid = tid >> 5;
    int i = blockIdx.x * 1024 + tid;
    int v = (i < N_NODES) ? deg[i] : 0;
    int x = v;
#pragma unroll
    for (int d = 1; d < 32; d <<= 1) {
        int t = __shfl_up_sync(0xffffffffu, x, d);
        if (lane >= d) x += t;
    }
    if (lane == 31) warp_sums[wid] = x;
    __syncthreads();
    if (wid == 0) {
        int s = warp_sums[lane];
#pragma unroll
        for (int d = 1; d < 32; d <<= 1) {
            int t = __shfl_up_sync(0xffffffffu, s, d);
            if (lane >= d) s += t;
        }
        warp_sums[lane] = s;
    }
    __syncthreads();
    int pre = (wid > 0) ? warp_sums[wid - 1] : 0;
    if (i < N_NODES) rowptr[i] = pre + x - v;
    if (tid == 1023) bsum[blockIdx.x] = pre + x;
}

__global__ void k_scan2(const int* __restrict__ bsum, int* __restrict__ bsumex,
                        int* __restrict__ rowptr, int nb) {
    __shared__ int warp_sums[4];
    int tid = threadIdx.x, lane = tid & 31, wid = tid >> 5;
    int v = (tid < nb) ? bsum[tid] : 0;
    int x = v;
#pragma unroll
    for (int d = 1; d < 32; d <<= 1) {
        int t = __shfl_up_sync(0xffffffffu, x, d);
        if (lane >= d) x += t;
    }
    if (lane == 31) warp_sums[wid] = x;
    __syncthreads();
    int off = 0;
    for (int w = 0; w < wid; w++) off += warp_sums[w];
    if (tid < nb) bsumex[tid] = off + x - v;
    if (tid == 127) rowptr[N_NODES] = off + x;
}

__global__ void k_scan3(int* __restrict__ rowptr, const int* __restrict__ bsumex,
                        int* __restrict__ cursor) {
    int i = blockIdx.x * blockDim.x + threadIdx.x;
    if (i < N_NODES) {
        int v = rowptr[i] + bsumex[i >> 10];
        rowptr[i] = v;
        cursor[i] = v;
    }
}

__global__ void k_place(const void* __restrict__ eraw, const float* __restrict__ ea,
                        int* __restrict__ cursor, Edge* __restrict__ e2) {
    int e = blockIdx.x * blockDim.x + threadIdx.x;
    if (e >= N_EDGES) return;
    int s, d;
    if (g_is64) {
        s = (int)((const long long*)eraw)[e];
        d = (int)((const long long*)eraw)[N_EDGES + e];
    } else {
        s = ((const int*)eraw)[e];
        d = ((const int*)eraw)[N_EDGES + e];
    }
    if ((unsigned)s >= N_NODES || (unsigned)d >= N_NODES) return;
    int pos = atomicAdd(&cursor[d], 1);
    Edge ed; ed.s = s; ed.w = ea[e];
    e2[pos] = ed;
}

// ---------------- single fused weight-prep kernel ----------------
__device__ __forceinline__ void prep_elem(const float* src, __nv_bfloat16* d16,
                                          int R, int K, int KP, int trans, int idx) {
    int r = idx / KP, k = idx - r * KP;
    float v = 0.f;
    if (k < K) v = trans ? src[k * R + r] : src[r * K + k];
    __nv_bfloat16 h = __float2bfloat16(v);
    d16[r * KP + k]          = h;
    d16[R * KP + r * KP + k] = __float2bfloat16(v - __bfloat162float(h));
}

__global__ void k_prep_all(const float* __restrict__ W1, const float* __restrict__ Wih1,
                           const float* __restrict__ Whh1, const float* __restrict__ W2,
                           const float* __restrict__ Wih2, const float* __restrict__ Whh2,
                           const float* __restrict__ fc1w, const float* __restrict__ fc2w,
                           unsigned char* __restrict__ wimg, float* __restrict__ fc2T) {
    int idx = blockIdx.x * blockDim.x + threadIdx.x;
    if (idx < 3840) {
        int i = idx / 1280, j = idx - i * 1280;
        prep_elem(W1 + i * 1024, (__nv_bfloat16*)(wimg + OFF_W1 + i * 5120), 32, 32, 40, 1, j);
    } else if (idx < 7680) {
        prep_elem(Wih1, (__nv_bfloat16*)(wimg + OFF_WIH1), 96, 32, 40, 0, idx - 3840);
    } else if (idx < 11520) {
        prep_elem(Whh1, (__nv_bfloat16*)(wimg + OFF_WHH1), 96, 32, 40, 0, idx - 7680);
    } else if (idx < 25344) {
        int j = idx - 11520;
        int i = j / 4608; j -= i * 4608;
        prep_elem(W2 + i * 4096, (__nv_bfloat16*)(wimg + OFF_W2 + i * 18432), 64, 64, 72, 1, j);
    } else if (idx < 39168) {
        prep_elem(Wih2, (__nv_bfloat16*)(wimg + OFF_WIH2), 192, 64, 72, 0, idx - 25344);
    } else if (idx < 52992) {
        prep_elem(Whh2, (__nv_bfloat16*)(wimg + OFF_WHH2), 192, 64, 72, 0, idx - 39168);
    } else if (idx < 62208) {
        prep_elem(fc1w, (__nv_bfloat16*)(wimg + OFF_FC1), 128, 64, 72, 0, idx - 52992);
    } else if (idx < 63488) {
        int j = idx - 62208;
        int r = j / 128, k = j - r * 128;
        fc2T[k * 10 + r] = fc2w[j];
    }
}

__global__ void k_init_h(const float* __restrict__ x, float* __restrict__ h) {
    int i = blockIdx.x * blockDim.x + threadIdx.x;
    if (i < N_NODES * 32) {
        int n = i >> 5, c = i & 31;
        h[i] = (c < 16) ? x[n * 16 + c] : 0.f;
    }
}

__global__ void k_pad_elu(const float* __restrict__ src, float* __restrict__ dst) {
    int i = blockIdx.x * blockDim.x + threadIdx.x;
    if (i < N_NODES * 64) {
        int n = i >> 6, c = i & 63;
        dst[i] = (c < 32) ? eluf_(src[n * 32 + c]) : 0.f;
    }
}

// ---------------- HMMA bf16x3 GEMM (round-0 msg) ----------------
template <int K, int RC>
__global__ void __launch_bounds__(256)
tgemm(const float* __restrict__ X, const __nv_bfloat16* __restrict__ Bh,
      const __nv_bfloat16* __restrict__ Bl, float* __restrict__ Y, int N, int Rtot) {
    using namespace nvcuda;
    constexpr int KP = K + 8;
    extern __shared__ unsigned char smem[];
    __nv_bfloat16* sAh = (__nv_bfloat16*)smem;
    __nv_bfloat16* sAl = sAh + 128 * KP;
    __nv_bfloat16* sBh = sAl + 128 * KP;
    __nv_bfloat16* sBl = sBh + RC * KP;
    float* sEp = (float*)smem;

    int tid = threadIdx.x, wid = tid >> 5;
    int n0 = blockIdx.x * 128;
    int c0 = blockIdx.y * RC;

    {
        const uint4* bh = (const uint4*)(Bh + (size_t)c0 * KP);
        const uint4* bl = (const uint4*)(Bl + (size_t)c0 * KP);
        uint4* dh = (uint4*)sBh;
        uint4* dl = (uint4*)sBl;
        for (int i = tid; i < (RC * KP) / 8; i += 256) { dh[i] = bh[i]; dl[i] = bl[i]; }
    }
    for (int i = tid; i < 128 * K; i += 256) {
        int r = i / K, k = i - r * K;
        int nn = n0 + r;
        float v = (nn < N) ? X[(size_t)nn * K + k] : 0.f;
        __nv_bfloat16 h = __float2bfloat16(v);
        sAh[r * KP + k] = h;
        sAl[r * KP + k] = __float2bfloat16(v - __bfloat162float(h));
    }
    __syncthreads();

    wmma::fragment<wmma::accumulator, 16, 16, 16, float> acc[RC / 16];
#pragma unroll
    for (int nc = 0; nc < RC / 16; nc++) wmma::fill_fragment(acc[nc], 0.f);

    int row0 = wid * 16;
#pragma unroll
    for (int kc = 0; kc < K / 16; kc++) {
        wmma::fragment<wmma::matrix_a, 16, 16, 16, __nv_bfloat16, wmma::row_major> ah, al;
        wmma::load_matrix_sync(ah, sAh + row0 * KP + kc * 16, KP);
        wmma::load_matrix_sync(al, sAl + row0 * KP + kc * 16, KP);
#pragma unroll
        for (int nc = 0; nc < RC / 16; nc++) {
            wmma::fragment<wmma::matrix_b, 16, 16, 16, __nv_bfloat16, wmma::col_major> bh, bl;
            wmma::load_matrix_sync(bh, sBh + nc * 16 * KP + kc * 16, KP);
            wmma::load_matrix_sync(bl, sBl + nc * 16 * KP + kc * 16, KP);
            wmma::mma_sync(acc[nc], ah, bh, acc[nc]);
            wmma::mma_sync(acc[nc], ah, bl, acc[nc]);
            wmma::mma_sync(acc[nc], al, bh, acc[nc]);
        }
    }

    __syncthreads();
#pragma unroll
    for (int nc = 0; nc < RC / 16; nc++) {
        wmma::store_matrix_sync(sEp + row0 * 20, acc[nc], 20, wmma::mem_row_major);
        __syncthreads();
        for (int i = tid; i < 128 * 16; i += 256) {
            int r = i >> 4, c = i & 15;
            int nn = n0 + r;
            if (nn < N) Y[(size_t)nn * Rtot + c0 + nc * 16 + c] = sEp[r * 20 + c];
        }
        __syncthreads();
    }
}

// ---------------- CSR gather-max (float4, node-range offset) ----------------
template <int C>
__global__ void k_gather(const float* __restrict__ m, const int* __restrict__ rowptr,
                         const Edge* __restrict__ e2, float* __restrict__ agg, int nbase) {
    int cx = threadIdx.x;
    int n = nbase + blockIdx.x * blockDim.y + threadIdx.y;
    if (n >= N_NODES) return;
    int beg = rowptr[n], end = rowptr[n + 1];
    float4 a0 = make_float4(-INFINITY, -INFINITY, -INFINITY, -INFINITY);
    float4 a1 = a0, a2 = a0, a3 = a0;
    int e = beg;
    for (; e + 3 < end; e += 4) {
        Edge d0 = e2[e], d1 = e2[e + 1], d2 = e2[e + 2], d3 = e2[e + 3];
        float4 v0 = *(const float4*)&m[(size_t)d0.s * C + 4 * cx];
        float4 v1 = *(const float4*)&m[(size_t)d1.s * C + 4 * cx];
        float4 v2 = *(const float4*)&m[(size_t)d2.s * C + 4 * cx];
        float4 v3 = *(const float4*)&m[(size_t)d3.s * C + 4 * cx];
        a0.x = fmaxf(a0.x, v0.x * d0.w); a0.y = fmaxf(a0.y, v0.y * d0.w);
        a0.z = fmaxf(a0.z, v0.z * d0.w); a0.w = fmaxf(a0.w, v0.w * d0.w);
        a1.x = fmaxf(a1.x, v1.x * d1.w); a1.y = fmaxf(a1.y, v1.y * d1.w);
        a1.z = fmaxf(a1.z, v1.z * d1.w); a1.w = fmaxf(a1.w, v1.w * d1.w);
        a2.x = fmaxf(a2.x, v2.x * d2.w); a2.y = fmaxf(a2.y, v2.y * d2.w);
        a2.z = fmaxf(a2.z, v2.z * d2.w); a2.w = fmaxf(a2.w, v2.w * d2.w);
        a3.x = fmaxf(a3.x, v3.x * d3.w); a3.y = fmaxf(a3.y, v3.y * d3.w);
        a3.z = fmaxf(a3.z, v3.z * d3.w); a3.w = fmaxf(a3.w, v3.w * d3.w);
    }
    for (; e < end; e++) {
        Edge d0 = e2[e];
        float4 v0 = *(const float4*)&m[(size_t)d0.s * C + 4 * cx];
        a0.x = fmaxf(a0.x, v0.x * d0.w); a0.y = fmaxf(a0.y, v0.y * d0.w);
        a0.z = fmaxf(a0.z, v0.z * d0.w); a0.w = fmaxf(a0.w, v0.w * d0.w);
    }
    float4 r;
    r.x = fmaxf(fmaxf(a0.x, a1.x), fmaxf(a2.x, a3.x));
    r.y = fmaxf(fmaxf(a0.y, a1.y), fmaxf(a2.y, a3.y));
    r.z = fmaxf(fmaxf(a0.z, a1.z), fmaxf(a2.z, a3.z));
    r.w = fmaxf(fmaxf(a0.w, a1.w), fmaxf(a2.w, a3.w));
    if (!isfinite(r.x)) r.x = 0.f;
    if (!isfinite(r.y)) r.y = 0.f;
    if (!isfinite(r.z)) r.z = 0.f;
    if (!isfinite(r.w)) r.w = 0.f;
    *(float4*)&agg[(size_t)n * C + 4 * cx] = r;
}

// ---------------- fused GRU (8 warps) + optional next-round msg GEMM ----------------
// R15 structure; for gates 0/1 accI+accH summed in registers -> single gI store/read.
template <int C>
__global__ void __launch_bounds__(256)
k_gru_mega(const float* __restrict__ agg, float* __restrict__ h,
           const __nv_bfloat16* __restrict__ Wih_h, const __nv_bfloat16* __restrict__ Wih_l,
           const __nv_bfloat16* __restrict__ Whh_h, const __nv_bfloat16* __restrict__ Whh_l,
           const float* __restrict__ bih, const float* __restrict__ bhh,
           const __nv_bfloat16* __restrict__ Wn_h, const __nv_bfloat16* __restrict__ Wn_l,
           float* __restrict__ mout, int nbase, int N) {
    using namespace nvcuda;
    constexpr int KP = C + 8;
    constexpr int LP = C + 8;
    constexpr int NC = C / 16;
    constexpr int NCW = (NC >= 2) ? NC / 2 : 1;
    constexpr int ABYTES = 4 * 64 * KP * 2;
    constexpr int BBYTES = 4 * C * KP * 2;
    constexpr int GBYTES = 2 * 64 * LP * 4;
    constexpr int WBYTES = (BBYTES > GBYTES) ? BBYTES : GBYTES;
    extern __shared__ unsigned char smem[];
    __nv_bfloat16* sAh = (__nv_bfloat16*)smem;
    __nv_bfloat16* sAl = sAh + 64 * KP;
    __nv_bfloat16* sHh = sAl + 64 * KP;
    __nv_bfloat16* sHl = sHh + 64 * KP;
    unsigned char* wreg = smem + ABYTES;
    __nv_bfloat16* sBih_h = (__nv_bfloat16*)wreg;
    __nv_bfloat16* sBih_l = sBih_h + C * KP;
    __nv_bfloat16* sBhh_h = sBih_l + C * KP;
    __nv_bfloat16* sBhh_l = sBhh_h + C * KP;
    float* gI = (float*)wreg;
    float* gH = gI + 64 * LP;
    float* sR = (float*)(smem + ABYTES + WBYTES);
    float* sZ = sR + 64 * C;

    int tid = threadIdx.x, wid = tid >> 5;
    int n0 = nbase + blockIdx.x * 64;
    int row0 = (wid >> 1) * 16;
    int ncb = (NC >= 2) ? (wid & 1) * NCW : 0;
    bool nc_active = (NC >= 2) || ((wid & 1) == 0);

    for (int i = tid; i < 64 * C; i += 256) {
        int r = i / C, k = i - r * C;
        int nn = n0 + r;
        float va = (nn < N) ? agg[(size_t)nn * C + k] : 0.f;
        float vh = (nn < N) ? h[(size_t)nn * C + k] : 0.f;
        __nv_bfloat16 ah = __float2bfloat16(va);
        sAh[r * KP + k] = ah;
        sAl[r * KP + k] = __float2bfloat16(va - __bfloat162float(ah));
        __nv_bfloat16 hh = __float2bfloat16(vh);
        sHh[r * KP + k] = hh;
        sHl[r * KP + k] = __float2bfloat16(vh - __bfloat162float(hh));
    }
    __syncthreads();

#pragma unroll
    for (int g = 0; g < 3; g++) {
        {
            const uint4* bih_h = (const uint4*)(Wih_h + (size_t)g * C * KP);
            const uint4* bih_l = (const uint4*)(Wih_l + (size_t)g * C * KP);
            const uint4* bhh_h = (const uint4*)(Whh_h + (size_t)g * C * KP);
            const uint4* bhh_l = (const uint4*)(Whh_l + (size_t)g * C * KP);
            uint4* d0 = (uint4*)sBih_h; uint4* d1 = (uint4*)sBih_l;
            uint4* d2 = (uint4*)sBhh_h; uint4* d3 = (uint4*)sBhh_l;
            for (int i = tid; i < (C * KP) / 8; i += 256) {
                d0[i] = bih_h[i]; d1[i] = bih_l[i];
                d2[i] = bhh_h[i]; d3[i] = bhh_l[i];
            }
        }
        __syncthreads();

        wmma::fragment<wmma::accumulator, 16, 16, 16, float> accI[NCW], accH[NCW];
#pragma unroll
        for (int j = 0; j < NCW; j++) {
            wmma::fill_fragment(accI[j], 0.f);
            wmma::fill_fragment(accH[j], 0.f);
        }
        if (nc_active) {
#pragma unroll
            for (int kc = 0; kc < C / 16; kc++) {
                wmma::fragment<wmma::matrix_a, 16, 16, 16, __nv_bfloat16, wmma::row_major> ah, al, hh, hl;
                wmma::load_matrix_sync(ah, sAh + row0 * KP + kc * 16, KP);
                wmma::load_matrix_sync(al, sAl + row0 * KP + kc * 16, KP);
                wmma::load_matrix_sync(hh, sHh + row0 * KP + kc * 16, KP);
                wmma::load_matrix_sync(hl, sHl + row0 * KP + kc * 16, KP);
#pragma unroll
                for (int j = 0; j < NCW; j++) {
                    int nc = ncb + j;
                    wmma::fragment<wmma::matrix_b, 16, 16, 16, __nv_bfloat16, wmma::col_major> bh, bl;
                    wmma::load_matrix_sync(bh, sBih_h + nc * 16 * KP + kc * 16, KP);
                    wmma::load_matrix_sync(bl, sBih_l + nc * 16 * KP + kc * 16, KP);
                    wmma::mma_sync(accI[j], ah, bh, accI[j]);
                    wmma::mma_sync(accI[j], ah, bl, accI[j]);
                    wmma::mma_sync(accI[j], al, bh, accI[j]);
                    wmma::load_matrix_sync(bh, sBhh_h + nc * 16 * KP + kc * 16, KP);
                    wmma::load_matrix_sync(bl, sBhh_l + nc * 16 * KP + kc * 16, KP);
                    wmma::mma_sync(accH[j], hh, bh, accH[j]);
                    wmma::mma_sync(accH[j], hh, bl, accH[j]);
                    wmma::mma_sync(accH[j], hl, bh, accH[j]);
                }
            }
        }
        __syncthreads();

        if (nc_active) {
#pragma unroll
            for (int j = 0; j < NCW; j++) {
                int nc = ncb + j;
                if (g < 2) {
                    // gates r/z only need the sum: merge in registers, single store
#pragma unroll
                    for (int t = 0; t < accI[j].num_elements; t++)
                        accI[j].x[t] += accH[j].x[t];
                    wmma::store_matrix_sync(gI + row0 * LP + nc * 16, accI[j], LP, wmma::mem_row_major);
                } else {
                    wmma::store_matrix_sync(gI + row0 * LP + nc * 16, accI[j], LP, wmma::mem_row_major);
                    wmma::store_matrix_sync(gH + row0 * LP + nc * 16, accH[j], LP, wmma::mem_row_major);
                }
            }
        }
        __syncthreads();

        for (int i = tid; i < 64 * C; i += 256) {
            int r = i / C, c = i - r * C;
            if (g == 0) {
                sR[i] = fsig_(gI[r * LP + c] + bih[c] + bhh[c]);
            } else if (g == 1) {
                sZ[i] = fsig_(gI[r * LP + c] + bih[C + c] + bhh[C + c]);
            } else {
                float vi = gI[r * LP + c] + bih[2 * C + c];
                float vh = gH[r * LP + c] + bhh[2 * C + c];
                int nn = n0 + r;
                float hnew = 0.f;
                if (nn < N) {
                    float rr = sR[i], zz = sZ[i];
                    float nv = ftanh_(vi + rr * vh);
                    float hv = h[(size_t)nn * C + c];
                    hnew = (1.f - zz) * nv + zz * hv;
                    h[(size_t)nn * C + c] = hnew;
                }
                __nv_bfloat16 hh2 = __float2bfloat16(hnew);
                sAh[r * KP + c] = hh2;
                sAl[r * KP + c] = __float2bfloat16(hnew - __bfloat162float(hh2));
            }
        }
        __syncthreads();
    }

    // ---- phase 2: m_next = h' @ Wn^T ----
    if (mout != nullptr) {
        {
            const uint4* wh = (const uint4*)Wn_h;
            const uint4* wl = (const uint4*)Wn_l;
            uint4* d0 = (uint4*)sBih_h;
            uint4* d1 = (uint4*)sBih_l;
            for (int i = tid; i < (C * KP) / 8; i += 256) { d0[i] = wh[i]; d1[i] = wl[i]; }
        }
        __syncthreads();

        wmma::fragment<wmma::accumulator, 16, 16, 16, float> accM[NCW];
#pragma unroll
        for (int j = 0; j < NCW; j++) wmma::fill_fragment(accM[j], 0.f);
        if (nc_active) {
#pragma unroll
            for (int kc = 0; kc < C / 16; kc++) {
                wmma::fragment<wmma::matrix_a, 16, 16, 16, __nv_bfloat16, wmma::row_major> ah, al;
                wmma::load_matrix_sync(ah, sAh + row0 * KP + kc * 16, KP);
                wmma::load_matrix_sync(al, sAl + row0 * KP + kc * 16, KP);
#pragma unroll
                for (int j = 0; j < NCW; j++) {
                    int nc = ncb + j;
                    wmma::fragment<wmma::matrix_b, 16, 16, 16, __nv_bfloat16, wmma::col_major> bh, bl;
                    wmma::load_matrix_sync(bh, sBih_h + nc * 16 * KP + kc * 16, KP);
                    wmma::load_matrix_sync(bl, sBih_l + nc * 16 * KP + kc * 16, KP);
                    wmma::mma_sync(accM[j], ah, bh, accM[j]);
                    wmma::mma_sync(accM[j], ah, bl, accM[j]);
                    wmma::mma_sync(accM[j], al, bh, accM[j]);
                }
            }
        }
        __syncthreads();
        if (nc_active) {
#pragma unroll
            for (int j = 0; j < NCW; j++) {
                int nc = ncb + j;
                wmma::store_matrix_sync(gI + row0 * LP + nc * 16, accM[j], LP, wmma::mem_row_major);
            }
        }
        __syncthreads();
        for (int i = tid; i < 64 * C; i += 256) {
            int r = i / C, c = i - r * C;
            int nn = n0 + r;
            if (nn < N) mout[(size_t)nn * C + c] = gI[r * LP + c];
        }
    }
}

// ---------------- fused head: fc1 (elu in/out) + fc2 + log_softmax ----------------
__global__ void __launch_bounds__(256)
k_head(const float* __restrict__ X, const __nv_bfloat16* __restrict__ Bh,
       const __nv_bfloat16* __restrict__ Bl, const float* __restrict__ fc1b,
       const float* __restrict__ fc2t, const float* __restrict__ fc2b,
       float* __restrict__ out, int N) {
    using namespace nvcuda;
    constexpr int KP = 72;
    constexpr int HLD = 136;
    extern __shared__ unsigned char smem[];
    __nv_bfloat16* sAh = (__nv_bfloat16*)smem;
    __nv_bfloat16* sAl = sAh + 128 * KP;
    __nv_bfloat16* sBh = sAl + 128 * KP;
    __nv_bfloat16* sBl = sBh + 128 * KP;
    float* sHid = (float*)smem;
    float* sW2  = (float*)(smem + 73728);
    float* sB1  = sW2 + 1280;
    float* sB2  = sB1 + 128;

    int tid = threadIdx.x, wid = tid >> 5, lane = tid & 31;
    int n0 = blockIdx.x * 128;

    {
        const uint4* bh = (const uint4*)Bh;
        const uint4* bl = (const uint4*)Bl;
        uint4* dh = (uint4*)sBh;
        uint4* dl = (uint4*)sBl;
        for (int i = tid; i < (128 * KP) / 8; i += 256) { dh[i] = bh[i]; dl[i] = bl[i]; }
    }
    for (int i = tid; i < 1280; i += 256) sW2[i] = fc2t[i];
    if (tid < 128) sB1[tid] = fc1b[tid];
    if (tid < 10)  sB2[tid] = fc2b[tid];
    for (int i = tid; i < 128 * 64; i += 256) {
        int r = i >> 6, k = i & 63;
        int nn = n0 + r;
        float v = (nn < N) ? eluf_(X[(size_t)nn * 64 + k]) : 0.f;
        __nv_bfloat16 h = __float2bfloat16(v);
        sAh[r * KP + k] = h;
        sAl[r * KP + k] = __float2bfloat16(v - __bfloat162float(h));
    }
    __syncthreads();

    wmma::fragment<wmma::accumulator, 16, 16, 16, float> acc[8];
#pragma unroll
    for (int nc = 0; nc < 8; nc++) wmma::fill_fragment(acc[nc], 0.f);

    int row0 = wid * 16;
#pragma unroll
    for (int kc = 0; kc < 4; kc++) {
        wmma::fragment<wmma::matrix_a, 16, 16, 16, __nv_bfloat16, wmma::row_major> ah, al;
        wmma::load_matrix_sync(ah, sAh + row0 * KP + kc * 16, KP);
        wmma::load_matrix_sync(al, sAl + row0 * KP + kc * 16, KP);
#pragma unroll
        for (int nc = 0; nc < 8; nc++) {
            wmma::fragment<wmma::matrix_b, 16, 16, 16, __nv_bfloat16, wmma::col_major> bh, bl;
            wmma::load_matrix_sync(bh, sBh + nc * 16 * KP + kc * 16, KP);
            wmma::load_matrix_sync(bl, sBl + nc * 16 * KP + kc * 16, KP);
            wmma::mma_sync(acc[nc], ah, bh, acc[nc]);
            wmma::mma_sync(acc[nc], ah, bl, acc[nc]);
            wmma::mma_sync(acc[nc], al, bh, acc[nc]);
        }
    }
    __syncthreads();

#pragma unroll
    for (int nc = 0; nc < 8; nc++)
        wmma::store_matrix_sync(sHid + row0 * HLD + nc * 16, acc[nc], HLD, wmma::mem_row_major);
    __syncthreads();

    for (int nn = wid * 16; nn < wid * 16 + 16; nn++) {
        int node = n0 + nn;
        if (node >= N) continue;
        float a[10];
#pragma unroll
        for (int j = 0; j < 10; j++) a[j] = 0.f;
#pragma unroll
        for (int kk = 0; kk < 4; kk++) {
            int k = lane + kk * 32;
            float xv = eluf_(sHid[nn * HLD + k] + sB1[k]);
            const float* w = sW2 + k * 10;
#pragma unroll
            for (int j = 0; j < 10; j++) a[j] = fmaf(xv, w[j], a[j]);
        }
#pragma unroll
        for (int j = 0; j < 10; j++)
            for (int off = 16; off; off >>= 1) a[j] += __shfl_xor_sync(0xffffffffu, a[j], off);
        float mx = -INFINITY;
#pragma unroll
        for (int j = 0; j < 10; j++) { a[j] += sB2[j]; mx = fmaxf(mx, a[j]); }
        float se = 0.f;
#pragma unroll
        for (int j = 0; j < 10; j++) se += ex2a_(LOG2E * (a[j] - mx));
        float lse = mx + LN2 * lg2a_(se);
        if (lane < 10) out[(size_t)node * 10 + lane] = a[lane] - lse;
    }
}

// ---------------- launch ----------------
static inline int gdiv(int n) { return (n + 255) / 256; }

extern "C" void kernel_launch(void* const* d_in, const int* in_sizes, int n_in,
                              void* d_out, int out_size) {
    const float* x    = (const float*)d_in[0];
    const void*  eraw = d_in[1];
    const float* ea   = (const float*)d_in[2];
    const float* W1   = (const float*)d_in[3];
    const float* Wih1 = (const float*)d_in[4];
    const float* Whh1 = (const float*)d_in[5];
    const float* bih1 = (const float*)d_in[6];
    const float* bhh1 = (const float*)d_in[7];
    const float* W2   = (const float*)d_in[8];
    const float* Wih2 = (const float*)d_in[9];
    const float* Whh2 = (const float*)d_in[10];
    const float* bih2 = (const float*)d_in[11];
    const float* bhh2 = (const float*)d_in[12];
    const float* fc1w = (const float*)d_in[13];
    const float* fc1b = (const float*)d_in[14];
    const float* fc2w = (const float*)d_in[15];
    const float* fc2b = (const float*)d_in[16];
    float* out = (float*)d_out;

    float *hA, *hB, *m, *agg, *fc2T;
    unsigned char* wimg;
    Edge* e2;
    int *deg, *rowptr, *cursor, *bsum, *bsumex;
    cudaGetSymbolAddress((void**)&hA,    g_hA);
    cudaGetSymbolAddress((void**)&hB,    g_hB);
    cudaGetSymbolAddress((void**)&m,     g_m);
    cudaGetSymbolAddress((void**)&agg,   g_agg);
    cudaGetSymbolAddress((void**)&fc2T,  g_fc2T);
    cudaGetSymbolAddress((void**)&wimg,  g_wimg);
    cudaGetSymbolAddress((void**)&deg,   g_deg);
    cudaGetSymbolAddress((void**)&rowptr,g_rowptr);
    cudaGetSymbolAddress((void**)&cursor,g_cursor);
    cudaGetSymbolAddress((void**)&e2,    g_e2);
    cudaGetSymbolAddress((void**)&bsum,  g_bsum);
    cudaGetSymbolAddress((void**)&bsumex,g_bsumex);

    static cudaStream_t s1 = nullptr;
    static cudaEvent_t  ev[16];
    if (s1 == nullptr) {
        cudaStreamCreateWithFlags(&s1, cudaStreamNonBlocking);
        for (int i = 0; i < 16; i++)
            cudaEventCreateWithFlags(&ev[i], cudaEventDisableTiming);
    }
    const int E_FORK = 0, E_CSR = 1, E_M1 = 2, E_M2 = 3;
    int enext = 4;

    const int TB = 256;
    const int GM  = (N_NODES + 127) / 128;  // 782
    const int NB = (N_NODES + 1023) / 1024; // 98
    const int H1N = N_NODES - H0N;
    const int MB0 = H0N / 64;
    const int MB1 = (H1N + 63) / 64;

    const __nv_bfloat16* W1h[3];  const __nv_bfloat16* W1l[3];
    const __nv_bfloat16* W2h[3];  const __nv_bfloat16* W2l[3];
    for (int i = 0; i < 3; i++) {
        W1h[i] = (const __nv_bfloat16*)(wimg + OFF_W1 + i * 5120);
        W1l[i] = W1h[i] + 32 * 40;
        W2h[i] = (const __nv_bfloat16*)(wimg + OFF_W2 + i * 18432);
        W2l[i] = W2h[i] + 64 * 72;
    }
    const __nv_bfloat16* Wih1h = (const __nv_bfloat16*)(wimg + OFF_WIH1);
    const __nv_bfloat16* Wih1l = Wih1h + 96 * 40;
    const __nv_bfloat16* Whh1h = (const __nv_bfloat16*)(wimg + OFF_WHH1);
    const __nv_bfloat16* Whh1l = Whh1h + 96 * 40;
    const __nv_bfloat16* Wih2h = (const __nv_bfloat16*)(wimg + OFF_WIH2);
    const __nv_bfloat16* Wih2l = Wih2h + 192 * 72;
    const __nv_bfloat16* Whh2h = (const __nv_bfloat16*)(wimg + OFF_WHH2);
    const __nv_bfloat16* Whh2l = Whh2h + 192 * 72;
    const __nv_bfloat16* Fc1h  = (const __nv_bfloat16*)(wimg + OFF_FC1);
    const __nv_bfloat16* Fc1l  = Fc1h + 128 * 72;

    const int SM_32_32 = (128 + 32) * 40 * 4;
    const int SM_64_64 = (128 + 64) * 72 * 4;
    const int MEGA32 = 4 * 64 * 40 * 2 + 20480 + 2 * 64 * 32 * 4;
    const int MEGA64 = 4 * 64 * 72 * 2 + 36864 + 2 * 64 * 64 * 4;
    const int SM_HEAD = 73728 + (1280 + 128 + 16) * 4;
    cudaFuncSetAttribute(tgemm<64, 64>, cudaFuncAttributeMaxDynamicSharedMemorySize, SM_64_64);
    cudaFuncSetAttribute(k_gru_mega<32>, cudaFuncAttributeMaxDynamicSharedMemorySize, MEGA32);
    cudaFuncSetAttribute(k_gru_mega<64>, cudaFuncAttributeMaxDynamicSharedMemorySize, MEGA64);
    cudaFuncSetAttribute(k_head, cudaFuncAttributeMaxDynamicSharedMemorySize, SM_HEAD);

    // ---- fork: CSR build on s1, overlapped with prep/init/tgemm0 ----
    cudaEventRecord(ev[E_FORK], 0);
    cudaStreamWaitEvent(s1, ev[E_FORK], 0);
    k_sniff_zero<<<NB, 1024, 0, s1>>>(eraw, deg);
    k_count<<<gdiv(N_EDGES), TB, 0, s1>>>(eraw, deg);
    k_scan1<<<NB, 1024, 0, s1>>>(deg, rowptr, bsum);
    k_scan2<<<1, 128, 0, s1>>>(bsum, bsumex, rowptr, NB);
    k_scan3<<<gdiv(N_NODES), TB, 0, s1>>>(rowptr, bsumex, cursor);
    k_place<<<gdiv(N_EDGES), TB, 0, s1>>>(eraw, ea, cursor, e2);
    cudaEventRecord(ev[E_CSR], s1);

    // main chain
    k_prep_all<<<gdiv(63488), TB>>>(W1, Wih1, Whh1, W2, Wih2, Whh2, fc1w, fc2w, wimg, fc2T);
    k_init_h<<<gdiv(N_NODES * 32), TB>>>(x, hA);
    tgemm<32, 32><<<dim3(GM, 1), 256, SM_32_32>>>(hA, W1h[0], W1l[0], m, N_NODES, 32);
    cudaEventRecord(ev[E_M1], 0);

    cudaStreamWaitEvent(0, ev[E_CSR], 0);
    cudaStreamWaitEvent(s1, ev[E_M1], 0);

    // ---- layer 1 (C=32), halves on two streams ----
    for (int i = 0; i < 3; i++) {
        const __nv_bfloat16* wnh = (i < 2) ? W1h[i + 1] : nullptr;
        const __nv_bfloat16* wnl = (i < 2) ? W1l[i + 1] : nullptr;
        float* mo = (i < 2) ? m : nullptr;
        { dim3 blk(8, 32);
          k_gather<32><<<H0N / 32, blk, 0, 0>>>(m, rowptr, e2, agg, 0);
          k_gather<32><<<(H1N + 31) / 32, blk, 0, s1>>>(m, rowptr, e2, agg, H0N); }
        k_gru_mega<32><<<MB0, 256, MEGA32, 0>>>(agg, hA, Wih1h, Wih1l, Whh1h, Whh1l,
                                                bih1, bhh1, wnh, wnl, mo, 0, N_NODES);
        k_gru_mega<32><<<MB1, 256, MEGA32, s1>>>(agg, hA, Wih1h, Wih1l, Whh1h, Whh1l,
                                                 bih1, bhh1, wnh, wnl, mo, H0N, N_NODES);
        cudaEventRecord(ev[enext], 0);
        cudaEventRecord(ev[enext + 1], s1);
        cudaStreamWaitEvent(0, ev[enext + 1], 0);
        cudaStreamWaitEvent(s1, ev[enext], 0);
        enext += 2;
    }

    k_pad_elu<<<gdiv(N_NODES * 64), TB>>>(hA, hB);
    tgemm<64, 64><<<dim3(GM, 1), 256, SM_64_64>>>(hB, W2h[0], W2l[0], m, N_NODES, 64);
    cudaEventRecord(ev[E_M2], 0);
    cudaStreamWaitEvent(s1, ev[E_M2], 0);

    // ---- layer 2 (C=64), halves on two streams ----
    for (int i = 0; i < 3; i++) {
        const __nv_bfloat16* wnh = (i < 2) ? W2h[i + 1] : nullptr;
        const __nv_bfloat16* wnl = (i < 2) ? W2l[i + 1] : nullptr;
        float* mo = (i < 2) ? m : nullptr;
        { dim3 blk(16, 16);
          k_gather<64><<<H0N / 16, blk, 0, 0>>>(m, rowptr, e2, agg, 0);
          k_gather<64><<<(H1N + 15) / 16, blk, 0, s1>>>(m, rowptr, e2, agg, H0N); }
        k_gru_mega<64><<<MB0, 256, MEGA64, 0>>>(agg, hB, Wih2h, Wih2l, Whh2h, Whh2l,
                                                bih2, bhh2, wnh, wnl, mo, 0, N_NODES);
        k_gru_mega<64><<<MB1, 256, MEGA64, s1>>>(agg, hB, Wih2h, Wih2l, Whh2h, Whh2l,
                                                 bih2, bhh2, wnh, wnl, mo, H0N, N_NODES);
        cudaEventRecord(ev[enext], 0);
        cudaEventRecord(ev[enext + 1], s1);
        cudaStreamWaitEvent(0, ev[enext + 1], 0);
        cudaStreamWaitEvent(s1, ev[enext], 0);
        enext += 2;
    }

    // ---- fused head ----
    k_head<<<GM, 256, SM_HEAD>>>(hB, Fc1h, Fc1l, fc1b, fc2T, fc2b, out, N_NODES);
}